// round 7
// baseline (speedup 1.0000x reference)
#include <cuda_runtime.h>
#include <cuda_bf16.h>

#define R   2
#define TX  32
#define TY  4
#define TZ  2
#define SXT (TX + 2*R)   // 36
#define SYT (TY + 2*R)   // 8
#define SZT (TZ + 2*R)   // 6
#define NDIM 128
#define NVOX (NDIM*NDIM*NDIM)
#define NTHREADS (TX*TY*TZ)   // 256

using u64 = unsigned long long;
using u32 = unsigned int;

__device__ __forceinline__ u64 pk2(float lo, float hi) {
    u64 r; asm("mov.b64 %0, {%1, %2};" : "=l"(r) : "f"(lo), "f"(hi)); return r;
}
__device__ __forceinline__ void upk2(u64 v, float& lo, float& hi) {
    asm("mov.b64 {%0, %1}, %2;" : "=f"(lo), "=f"(hi) : "l"(v));
}
__device__ __forceinline__ u64 fma2(u64 a, u64 b, u64 c) {
    u64 d; asm("fma.rn.f32x2 %0, %1, %2, %3;" : "=l"(d) : "l"(a), "l"(b), "l"(c)); return d;
}
__device__ __forceinline__ u64 add2(u64 a, u64 b) {
    u64 d; asm("add.rn.f32x2 %0, %1, %2;" : "=l"(d) : "l"(a), "l"(b)); return d;
}

// One packed tap = 2 voxel-taps (batch0 lo lane, batch1 hi lane).
// arg(f32x2) --PRMT truncate--> bf16x2 --ex2.bf16x2--> bit-unpack to f32x2.
// No F2FP converter op: only EX2 touches the MUFU/XU port.
__device__ __forceinline__ void tap(u64 xk2, u64 s2, u64 ns2, u64 xcs2, u64 nxcs2,
                                    u64 b2, u64& num2, u64& den2)
{
    u64 p = fma2(xk2, ns2, xcs2);    // (xc - xk) * s   per lane
    u64 q = fma2(xk2, s2, nxcs2);    // (xk - xc) * s   per lane
    u64 a = fma2(p, q, b2);          // lgw_spatial - s^2 d^2  (log2 of weight)
    float alo, ahi; upk2(a, alo, ahi);
    u32 abl = __float_as_uint(alo);
    u32 abh = __float_as_uint(ahi);
    u32 h2;
    asm("prmt.b32 %0, %1, %2, 0x7632;" : "=r"(h2) : "r"(abl), "r"(abh)); // truncate-pack to bf16x2 (ALU)
    asm("ex2.approx.ftz.bf16x2 %0, %0;" : "+r"(h2));                     // sole MUFU op: 1 / 2 taps
    u32 wlo_b = h2 << 16;            // bf16 -> f32: pure shift (ALU)
    u32 whi_b = h2 & 0xFFFF0000u;    // bf16 -> f32: pure mask  (ALU)
    u64 w2 = pk2(__uint_as_float(wlo_b), __uint_as_float(whi_b));
    num2 = fma2(w2, xk2, num2);      // fp32 accumulation, both lanes
    den2 = add2(den2, w2);
}

__global__ __launch_bounds__(NTHREADS)
void bilateral3d_kernel(const float* __restrict__ in,
                        float* __restrict__ out,
                        const float* __restrict__ p_sx,
                        const float* __restrict__ p_sy,
                        const float* __restrict__ p_sz,
                        const float* __restrict__ p_cs)
{
    __shared__ float2 tile[SZT][SYT][SXT];   // 13824 B

    const float LOG2E = 1.4426950408889634f;
    // Truncation (round-toward-zero) pre-bias: scale all log2-domain coeffs by
    // (1 + 2^-9) so the bf16 truncation error is centered like round-nearest.
    const float KB = 1.0f + 1.0f / 512.0f;
    const float sx = *p_sx, sy = *p_sy, sz = *p_sz, cs = *p_cs;
    const float ax = -KB * LOG2E / (2.0f * sx * sx);
    const float ay = -KB * LOG2E / (2.0f * sy * sy);
    const float az = -KB * LOG2E / (2.0f * sz * sz);
    const float s  = sqrtf(KB * LOG2E / (2.0f * cs * cs));

    const int x0 = blockIdx.x * TX;
    const int y0 = blockIdx.y * TY;
    const int z0 = blockIdx.z * TZ;

    // ---- cooperative tile load, both batches packed, sentinel halo ----
    const float BIG = 1e18f;   // OOB: arg ~ -2.9e36 -> bf16 huge-negative -> ex2 -> exact 0
    const int tid = threadIdx.x + TX * (threadIdx.y + TY * threadIdx.z);
    float2* tflat = &tile[0][0][0];
    for (int i = tid; i < SZT*SYT*SXT; i += NTHREADS) {
        int lxx = i % SXT;
        int t   = i / SXT;
        int lyy = t % SYT;
        int lzz = t / SYT;
        int gx = x0 + lxx - R;
        int gy = y0 + lyy - R;
        int gz = z0 + lzz - R;
        float2 v = make_float2(BIG, BIG);
        if ((unsigned)gx < NDIM && (unsigned)gy < NDIM && (unsigned)gz < NDIM) {
            size_t g = ((size_t)gz * NDIM + gy) * NDIM + gx;
            v.x = in[g];
            v.y = in[g + NVOX];
        }
        tflat[i] = v;
    }
    __syncthreads();

    const float ax1 = ax, ax4 = 4.0f * ax;
    float wy[5];
    #pragma unroll
    for (int i = 0; i < 5; i++) {
        float d = (float)(i - R);
        wy[i] = d * d * ay;
    }

    const int lx = threadIdx.x, ly = threadIdx.y, lz = threadIdx.z;
    const float2 xc2 = tile[lz + R][ly + R][lx + R];
    const float xcs_lo = xc2.x * s, xcs_hi = xc2.y * s;
    const u64 s2    = pk2(s, s);
    const u64 ns2   = pk2(-s, -s);
    const u64 xcs2  = pk2(xcs_lo, xcs_hi);
    const u64 nxcs2 = pk2(-xcs_lo, -xcs_hi);

    u64 num2 = pk2(0.0f, 0.0f);
    u64 den2 = pk2(0.0f, 0.0f);

    #pragma unroll 1                       // keep register pressure down
    for (int dz = 0; dz < 5; dz++) {
        float dzf = (float)(dz - R);
        float wzv = dzf * dzf * az;
        #pragma unroll
        for (int dy = 0; dy < 5; dy++) {
            const float b0 = wy[dy] + wzv;
            const float b1 = b0 + ax1;
            const float b4 = b0 + ax4;
            const u64 b0_2 = pk2(b0, b0);
            const u64 b1_2 = pk2(b1, b1);
            const u64 b4_2 = pk2(b4, b4);
            const u64* row = reinterpret_cast<const u64*>(&tile[lz + dz][ly + dy][lx]);
            tap(row[0], s2, ns2, xcs2, nxcs2, b4_2, num2, den2);
            tap(row[1], s2, ns2, xcs2, nxcs2, b1_2, num2, den2);
            tap(row[2], s2, ns2, xcs2, nxcs2, b0_2, num2, den2);
            tap(row[3], s2, ns2, xcs2, nxcs2, b1_2, num2, den2);
            tap(row[4], s2, ns2, xcs2, nxcs2, b4_2, num2, den2);
        }
    }

    float nlo, nhi, dlo, dhi;
    upk2(num2, nlo, nhi);
    upk2(den2, dlo, dhi);

    const size_t o = ((size_t)(z0 + lz) * NDIM + (y0 + ly)) * NDIM + (x0 + lx);
    out[o]        = __fdividef(nlo, dlo);
    out[o + NVOX] = __fdividef(nhi, dhi);
}

extern "C" void kernel_launch(void* const* d_in, const int* in_sizes, int n_in,
                              void* d_out, int out_size)
{
    const float* img = (const float*)d_in[0];
    const float* psx = (const float*)d_in[1];
    const float* psy = (const float*)d_in[2];
    const float* psz = (const float*)d_in[3];
    const float* pcs = (const float*)d_in[4];
    float* outp = (float*)d_out;

    dim3 block(TX, TY, TZ);
    dim3 grid(NDIM / TX, NDIM / TY, NDIM / TZ);
    bilateral3d_kernel<<<grid, block>>>(img, outp, psx, psy, psz, pcs);
}

// round 8
// speedup vs baseline: 1.0363x; 1.0363x over previous
#include <cuda_runtime.h>
#include <cuda_bf16.h>

#define R   2
#define TX  32
#define TY  4
#define TZ  2
#define SXT (TX + 2*R)   // 36
#define SYT (TY + 2*R)   // 8
#define SZT (TZ + 2*R)   // 6
#define NDIM 128
#define NVOX (NDIM*NDIM*NDIM)
#define NTHREADS (TX*TY*TZ)   // 256

using u64 = unsigned long long;
using u32 = unsigned int;

__device__ __forceinline__ u64 pk2(float lo, float hi) {
    u64 r; asm("mov.b64 %0, {%1, %2};" : "=l"(r) : "f"(lo), "f"(hi)); return r;
}
__device__ __forceinline__ void upk2(u64 v, float& lo, float& hi) {
    asm("mov.b64 {%0, %1}, %2;" : "=f"(lo), "=f"(hi) : "l"(v));
}
__device__ __forceinline__ u64 fma2(u64 a, u64 b, u64 c) {
    u64 d; asm("fma.rn.f32x2 %0, %1, %2, %3;" : "=l"(d) : "l"(a), "l"(b), "l"(c)); return d;
}
__device__ __forceinline__ u64 add2(u64 a, u64 b) {
    u64 d; asm("add.rn.f32x2 %0, %1, %2;" : "=l"(d) : "l"(a), "l"(b)); return d;
}

// One packed tap = 2 voxel-taps (batch0 lo lane, batch1 hi lane).
// Tile holds y = s*x, so p = ycs - y = s(xc-xk), q = y - ycs = -p (one add2).
// arg --PRMT truncate--> bf16x2 --ex2.bf16x2--> bit-unpack. Only EX2 on MUFU.
__device__ __forceinline__ void tap(u64 y2, u64 negone2, u64 ycs2, u64 nycs2,
                                    u64 b2, u64& num2, u64& den2)
{
    u64 p = fma2(y2, negone2, ycs2);   // s(xc - xk)
    u64 q = add2(y2, nycs2);           // s(xk - xc) = -p
    u64 a = fma2(p, q, b2);            // lgw_spatial - s^2 d^2
    float alo, ahi; upk2(a, alo, ahi);
    u32 abl = __float_as_uint(alo);
    u32 abh = __float_as_uint(ahi);
    u32 h2;
    asm("prmt.b32 %0, %1, %2, 0x7632;" : "=r"(h2) : "r"(abl), "r"(abh)); // bf16x2 truncate-pack
    asm("ex2.approx.ftz.bf16x2 %0, %0;" : "+r"(h2));
    u32 wlo_b = h2 << 16;
    u32 whi_b = h2 & 0xFFFF0000u;
    u64 w2 = pk2(__uint_as_float(wlo_b), __uint_as_float(whi_b));
    num2 = fma2(w2, y2, num2);         // accumulates w * (s*x); /s folded into epilogue
    den2 = add2(den2, w2);
}

__global__ __launch_bounds__(NTHREADS, 6)   // cap regs -> 6 CTAs/SM = 75% occ
void bilateral3d_kernel(const float* __restrict__ in,
                        float* __restrict__ out,
                        const float* __restrict__ p_sx,
                        const float* __restrict__ p_sy,
                        const float* __restrict__ p_sz,
                        const float* __restrict__ p_cs)
{
    __shared__ float2 tile[SZT][SYT][SXT];   // 13824 B, holds s*x per lane

    const float LOG2E = 1.4426950408889634f;
    const float KB = 1.0f + 1.0f / 512.0f;   // center bf16 truncation bias
    const float sx = *p_sx, sy = *p_sy, sz = *p_sz, cs = *p_cs;
    const float ax = -KB * LOG2E / (2.0f * sx * sx);
    const float ay = -KB * LOG2E / (2.0f * sy * sy);
    const float az = -KB * LOG2E / (2.0f * sz * sz);
    const float s  = sqrtf(KB * LOG2E / (2.0f * cs * cs));

    const int x0 = blockIdx.x * TX;
    const int y0 = blockIdx.y * TY;
    const int z0 = blockIdx.z * TZ;

    // ---- cooperative tile load (pre-scaled by s), sentinel halo ----
    const float BIG = 1e18f;   // s*BIG still huge -> arg -> -inf-ish -> w = exact 0
    const int tid = threadIdx.x + TX * (threadIdx.y + TY * threadIdx.z);
    float2* tflat = &tile[0][0][0];
    for (int i = tid; i < SZT*SYT*SXT; i += NTHREADS) {
        int lxx = i % SXT;
        int t   = i / SXT;
        int lyy = t % SYT;
        int lzz = t / SYT;
        int gx = x0 + lxx - R;
        int gy = y0 + lyy - R;
        int gz = z0 + lzz - R;
        float2 v = make_float2(BIG, BIG);
        if ((unsigned)gx < NDIM && (unsigned)gy < NDIM && (unsigned)gz < NDIM) {
            size_t g = ((size_t)gz * NDIM + gy) * NDIM + gx;
            v.x = in[g] * s;
            v.y = in[g + NVOX] * s;
        }
        tflat[i] = v;
    }
    __syncthreads();

    const float ax1 = ax, ax4 = 4.0f * ax;
    float wy[5];
    #pragma unroll
    for (int i = 0; i < 5; i++) {
        float d = (float)(i - R);
        wy[i] = d * d * ay;
    }

    const int lx = threadIdx.x, ly = threadIdx.y, lz = threadIdx.z;
    const float2 yc2 = tile[lz + R][ly + R][lx + R];   // already s*xc
    const u64 negone2 = pk2(-1.0f, -1.0f);
    const u64 ycs2    = pk2(yc2.x, yc2.y);
    const u64 nycs2   = pk2(-yc2.x, -yc2.y);

    u64 num2 = pk2(0.0f, 0.0f);
    u64 den2 = pk2(0.0f, 0.0f);

    #pragma unroll 1
    for (int dz = 0; dz < 5; dz++) {
        float dzf = (float)(dz - R);
        float wzv = dzf * dzf * az;
        #pragma unroll
        for (int dy = 0; dy < 5; dy++) {
            const float b0 = wy[dy] + wzv;
            const float b1 = b0 + ax1;
            const float b4 = b0 + ax4;
            const u64 b0_2 = pk2(b0, b0);
            const u64 b1_2 = pk2(b1, b1);
            const u64 b4_2 = pk2(b4, b4);
            const u64* row = reinterpret_cast<const u64*>(&tile[lz + dz][ly + dy][lx]);
            // batch the 5 row loads (MLP) before compute
            u64 r0 = row[0], r1 = row[1], r2 = row[2], r3 = row[3], r4 = row[4];
            tap(r0, negone2, ycs2, nycs2, b4_2, num2, den2);
            tap(r1, negone2, ycs2, nycs2, b1_2, num2, den2);
            tap(r2, negone2, ycs2, nycs2, b0_2, num2, den2);
            tap(r3, negone2, ycs2, nycs2, b1_2, num2, den2);
            tap(r4, negone2, ycs2, nycs2, b4_2, num2, den2);
        }
    }

    float nlo, nhi, dlo, dhi;
    upk2(num2, nlo, nhi);
    upk2(den2, dlo, dhi);

    const float inv_s = __fdividef(1.0f, s);
    const size_t o = ((size_t)(z0 + lz) * NDIM + (y0 + ly)) * NDIM + (x0 + lx);
    out[o]        = __fdividef(nlo, dlo) * inv_s;
    out[o + NVOX] = __fdividef(nhi, dhi) * inv_s;
}

extern "C" void kernel_launch(void* const* d_in, const int* in_sizes, int n_in,
                              void* d_out, int out_size)
{
    const float* img = (const float*)d_in[0];
    const float* psx = (const float*)d_in[1];
    const float* psy = (const float*)d_in[2];
    const float* psz = (const float*)d_in[3];
    const float* pcs = (const float*)d_in[4];
    float* outp = (float*)d_out;

    dim3 block(TX, TY, TZ);
    dim3 grid(NDIM / TX, NDIM / TY, NDIM / TZ);
    bilateral3d_kernel<<<grid, block>>>(img, outp, psx, psy, psz, pcs);
}